// round 8
// baseline (speedup 1.0000x reference)
#include <cuda_runtime.h>
#include <cuda_bf16.h>
#include <cstdint>

// ============================================================================
// LocalBranch round 8: bf16x3 mma.sync, term-major issue order (break the
// 3-deep accumulator RAW chains that capped issue at 30% in round 7).
// Structure otherwise identical to round 7 (623 us):
//  - per-graph CTA, 512 thr = 16 warps, warp tile 32x64 (or 32x32)
//  - x as hi/lo bf16 planes in SMEM; weights pre-split into __device__ image
//  - cp.async double-buffered k32 chunks; LN epilogues in fp32 registers
//  - Gram = Z @ Z^T same path; softmax/pool SIMT
// ============================================================================

namespace lb {

using u32 = uint32_t;

constexpr int TPB = 512, NODES = 128, IND = 64, HID = 256, OUTD = 128,
              NBLK = 3, NG = 1024;

// SMEM layout (bytes)
constexpr int XS_RS = 528;                 // x-plane row stride (264 bf16)
constexpr int XS_PL = 128 * XS_RS;         // 67584 per plane
constexpr int XS_HI = 0;
constexpr int XS_LO = XS_PL;
constexpr int RING  = 2 * XS_PL;           // 135168 (2 weight slots; later zT)
constexpr int SLOT  = 40960;
constexpr int SCR   = RING + 2 * SLOT;     // 217088
constexpr int SC_PART = SCR;               // float2[128*4]
constexpr int SC_SQ   = SCR + 4096;        // float[128]
constexpr int SC_S    = SCR + 4608;        // float[128]
constexpr int SC_W    = SCR + 5120;        // float[128]
constexpr int SMEM_BYTES = SCR + 5632;     // 222720

// Weight image: per GEMM, k32 chunks; chunk = [hi plane][lo plane],
// plane = N rows x 40 bf16 (80 B, padded) in n-major (W^T) order.
constexpr int IMG_STEM = 0;                           // 2 chunks x 40960
constexpr int IMG_BLK  = 81920;                       // 3 x 8 x 40960
constexpr int IMG_BLKSTR = 327680;
constexpr int IMG_HEAD = 1064960;                     // 8 x 20480
__device__ __align__(16) unsigned char g_wimg[1228800];

// ---------------- PTX helpers ----------------
__device__ __forceinline__ u32 s2u(const void* p) {
    u32 a;
    asm("{ .reg .u64 t; cvta.to.shared.u64 t, %1; cvt.u32.u64 %0, t; }"
        : "=r"(a) : "l"(p));
    return a;
}
__device__ __forceinline__ void ldsm4(u32* r, u32 addr) {
    asm volatile("ldmatrix.sync.aligned.m8n8.x4.shared.b16 {%0,%1,%2,%3}, [%4];"
                 : "=r"(r[0]), "=r"(r[1]), "=r"(r[2]), "=r"(r[3]) : "r"(addr));
}
__device__ __forceinline__ void mma16816(float* c, const u32* a, u32 b0, u32 b1) {
    asm volatile(
        "mma.sync.aligned.m16n8k16.row.col.f32.bf16.bf16.f32 "
        "{%0,%1,%2,%3}, {%4,%5,%6,%7}, {%8,%9}, {%0,%1,%2,%3};"
        : "+f"(c[0]), "+f"(c[1]), "+f"(c[2]), "+f"(c[3])
        : "r"(a[0]), "r"(a[1]), "r"(a[2]), "r"(a[3]), "r"(b0), "r"(b1));
}
__device__ __forceinline__ void cpa16(u32 dst, const void* src) {
    asm volatile("cp.async.cg.shared.global [%0], [%1], 16;"
                 :: "r"(dst), "l"(src) : "memory");
}
__device__ __forceinline__ void cp_commit() {
    asm volatile("cp.async.commit_group;" ::: "memory");
}
__device__ __forceinline__ void cp_wait1() {
    asm volatile("cp.async.wait_group 1;" ::: "memory");
}
__device__ __forceinline__ void cp_wait0() {
    asm volatile("cp.async.wait_group 0;" ::: "memory");
}

// ---------------- bf16 pack helpers ----------------
__device__ __forceinline__ u32 packbf(float x0, float x1) {
    unsigned short a = __bfloat16_as_ushort(__float2bfloat16(x0));
    unsigned short b = __bfloat16_as_ushort(__float2bfloat16(x1));
    return (u32)a | ((u32)b << 16);
}
__device__ __forceinline__ float bflo(u32 p) {
    return __bfloat162float(__ushort_as_bfloat16((unsigned short)(p & 0xffff)));
}
__device__ __forceinline__ float bfhi(u32 p) {
    return __bfloat162float(__ushort_as_bfloat16((unsigned short)(p >> 16)));
}

// ---------------- prep: weights -> split/transposed padded image ----------
__global__ void prep(const float* __restrict__ Wi, const float* __restrict__ Wb,
                     const float* __restrict__ Wo) {
    int idx = blockIdx.x * 256 + threadIdx.x;        // 245760 total
    const float* W; int k, n, N; long base; int cstr;
    if (idx < 16384) {
        W = Wi; N = 256; k = idx >> 8; n = idx & 255;
        base = IMG_STEM; cstr = 40960;
    } else if (idx < 212992) {
        int e = idx - 16384; int b = e >> 16; e &= 65535;
        W = Wb + (size_t)b * 65536; N = 256; k = e >> 8; n = e & 255;
        base = IMG_BLK + (long)b * IMG_BLKSTR; cstr = 40960;
    } else {
        int e = idx - 212992;
        W = Wo; N = 128; k = e >> 7; n = e & 127;
        base = IMG_HEAD; cstr = 20480;
    }
    float w = W[(size_t)k * N + n];
    __nv_bfloat16 h = __float2bfloat16(w);
    __nv_bfloat16 l = __float2bfloat16(w - __bfloat162float(h));
    long off = base + (long)(k >> 5) * cstr + (long)n * 80 + (k & 31) * 2;
    *(__nv_bfloat16*)(g_wimg + off) = h;
    *(__nv_bfloat16*)(g_wimg + off + (long)N * 80) = l;
}

// ---------------- staged GEMM: acc += X(planes) @ W(img), 3-term ----------
// Term-major issue: for each pair of n8x2 tiles, all 8 c-tiles get term t
// before any gets term t+1  -> no back-to-back accumulator RAW chains.
template<int N>   // 256 or 128
__device__ __forceinline__ void gemm_run(
    u32 smb, unsigned char* smc, const unsigned char* img, int nchunk,
    float (&acc)[2][8][4], int tid, int m0, int nq,
    int a_row, int a_kh, int b_n, int b_kh)
{
    constexpr int NP = N / 64;                 // ldsm-pairs of n8 tiles (4|2)
    constexpr int NH = NP / 2;                 // halves of 2 pairs
    constexpr int CB = N * 160;                // chunk bytes (2 planes)
    constexpr int LINES = CB / 16;
    const int n0 = nq * (N / 4);

    const u32 axh = smb + XS_HI + (u32)(m0 + a_row) * XS_RS + a_kh * 16;
    const u32 axl = axh + XS_PL;
    const u32 wtb = (u32)(n0 + b_n) * 80 + b_kh * 16;

#pragma unroll
    for (int mt = 0; mt < 2; ++mt)
#pragma unroll
        for (int nt = 0; nt < 8; ++nt)
#pragma unroll
            for (int e = 0; e < 4; ++e) acc[mt][nt][e] = 0.f;

    // issue chunk 0
    {
        u32 dst = smb + RING;
        const unsigned char* src = img;
        for (int i = tid; i < LINES; i += TPB) cpa16(dst + i * 16, src + i * 16);
        cp_commit();
    }

    for (int ch = 0; ch < nchunk; ++ch) {
        if (ch + 1 < nchunk) {
            u32 dst = smb + RING + ((ch + 1) & 1) * SLOT;
            const unsigned char* src = img + (size_t)(ch + 1) * CB;
            for (int i = tid; i < LINES; i += TPB) cpa16(dst + i * 16, src + i * 16);
            cp_commit();
            cp_wait1();
        } else {
            cp_wait0();
        }
        __syncthreads();
        const u32 slot = smb + RING + (ch & 1) * SLOT;
#pragma unroll
        for (int ks = 0; ks < 2; ++ks) {
            const u32 kb = (u32)ch * 64 + ks * 32;
            u32 ah0[4], ah1[4], al0[4], al1[4];
            ldsm4(ah0, axh + kb);
            ldsm4(ah1, axh + 16 * XS_RS + kb);
            ldsm4(al0, axl + kb);
            ldsm4(al1, axl + 16 * XS_RS + kb);
#pragma unroll
            for (int hf = 0; hf < NH; ++hf) {
                u32 bh[2][4], bl[2][4];
#pragma unroll
                for (int p = 0; p < 2; ++p) {
                    const u32 wa = slot + wtb
                                 + (u32)(hf * 2 + p) * 16 * 80 + ks * 32;
                    ldsm4(bh[p], wa);
                    ldsm4(bl[p], wa + N * 80);
                }
                // term 1: Ahi * Bhi  (8 independent c-tiles)
#pragma unroll
                for (int p = 0; p < 2; ++p)
#pragma unroll
                    for (int h = 0; h < 2; ++h) {
                        int nt = (hf * 2 + p) * 2 + h;
                        mma16816(acc[0][nt], ah0, bh[p][2*h], bh[p][2*h+1]);
                        mma16816(acc[1][nt], ah1, bh[p][2*h], bh[p][2*h+1]);
                    }
                // term 2: Alo * Bhi
#pragma unroll
                for (int p = 0; p < 2; ++p)
#pragma unroll
                    for (int h = 0; h < 2; ++h) {
                        int nt = (hf * 2 + p) * 2 + h;
                        mma16816(acc[0][nt], al0, bh[p][2*h], bh[p][2*h+1]);
                        mma16816(acc[1][nt], al1, bh[p][2*h], bh[p][2*h+1]);
                    }
                // term 3: Ahi * Blo
#pragma unroll
                for (int p = 0; p < 2; ++p)
#pragma unroll
                    for (int h = 0; h < 2; ++h) {
                        int nt = (hf * 2 + p) * 2 + h;
                        mma16816(acc[0][nt], ah0, bl[p][2*h], bl[p][2*h+1]);
                        mma16816(acc[1][nt], ah1, bl[p][2*h], bl[p][2*h+1]);
                    }
            }
        }
        __syncthreads();
    }
}

// ---------------- main kernel ----------------
__global__ void __launch_bounds__(TPB, 1)
fused(const float* __restrict__ H,
      const float* __restrict__ b_in, const float* __restrict__ g_in,
      const float* __restrict__ be_in,
      const float* __restrict__ bb, const float* __restrict__ gb,
      const float* __restrict__ betab,
      const float* __restrict__ b_out, const float* __restrict__ g_out,
      const float* __restrict__ be_out,
      float* __restrict__ out)
{
    extern __shared__ __align__(16) unsigned char smc[];
    const u32 smb = s2u(smc);
    const int tid = threadIdx.x, lane = tid & 31, w = tid >> 5;
    const int qr = lane >> 2, qc = lane & 3;
    const int mq = w & 3, nq = w >> 2;
    const int m0 = mq * 32;
    const int grp = lane >> 3, ri = lane & 7;
    const int a_row = (grp & 1) * 8 + ri, a_kh = grp >> 1;
    const int b_n = (grp >> 1) * 8 + ri,  b_kh = grp & 1;
    const int g = blockIdx.x;

    float2* part = (float2*)(smc + SC_PART);
    float* sqv = (float*)(smc + SC_SQ);
    float* ssm = (float*)(smc + SC_S);
    float* wsm = (float*)(smc + SC_W);

    // ---- stem A: H -> hi/lo bf16 planes (k = 0..63) ----
    {
        const int row = tid >> 2, c4 = tid & 3;
        const float4* hs = (const float4*)(H + (size_t)g * NODES * IND
                                           + (size_t)row * IND + c4 * 16);
        const u32 off = (u32)row * XS_RS + (u32)c4 * 32;
#pragma unroll
        for (int q = 0; q < 4; ++q) {
            float4 v = hs[q];
            u32 h0 = packbf(v.x, v.y), h1 = packbf(v.z, v.w);
            u32 l0 = packbf(v.x - bflo(h0), v.y - bfhi(h0));
            u32 l1 = packbf(v.z - bflo(h1), v.w - bfhi(h1));
            *(u32*)(smc + XS_HI + off + q * 8)     = h0;
            *(u32*)(smc + XS_HI + off + q * 8 + 4) = h1;
            *(u32*)(smc + XS_LO + off + q * 8)     = l0;
            *(u32*)(smc + XS_LO + off + q * 8 + 4) = l1;
        }
    }
    // (gemm_run's post-copy __syncthreads orders these STS before ldmatrix)

    float acc[2][8][4];

    // ---- LN(+relu,+residual) epilogue for N=256, rewrites x planes ----
    auto ep256 = [&](const float* bias, const float* gam, const float* bet,
                     bool res) {
        const int n0 = nq * 64;
        float s1[4] = {0.f, 0.f, 0.f, 0.f}, s2[4] = {0.f, 0.f, 0.f, 0.f};
#pragma unroll
        for (int nt = 0; nt < 8; ++nt) {
            float2 bp = *(const float2*)&bias[n0 + nt * 8 + qc * 2];
#pragma unroll
            for (int mt = 0; mt < 2; ++mt) {
                float* c = acc[mt][nt];
                c[0] += bp.x; c[1] += bp.y; c[2] += bp.x; c[3] += bp.y;
                s1[mt*2]   += c[0] + c[1];
                s2[mt*2]    = fmaf(c[0], c[0], fmaf(c[1], c[1], s2[mt*2]));
                s1[mt*2+1] += c[2] + c[3];
                s2[mt*2+1]  = fmaf(c[2], c[2], fmaf(c[3], c[3], s2[mt*2+1]));
            }
        }
#pragma unroll
        for (int r = 0; r < 4; ++r) {
            s1[r] += __shfl_xor_sync(0xffffffffu, s1[r], 1);
            s1[r] += __shfl_xor_sync(0xffffffffu, s1[r], 2);
            s2[r] += __shfl_xor_sync(0xffffffffu, s2[r], 1);
            s2[r] += __shfl_xor_sync(0xffffffffu, s2[r], 2);
        }
        if (qc == 0) {
#pragma unroll
            for (int r = 0; r < 4; ++r) {
                int row = m0 + (r >> 1) * 16 + (r & 1) * 8 + qr;
                part[row * 4 + nq] = make_float2(s1[r], s2[r]);
            }
        }
        __syncthreads();
        float mu[4], rs[4];
#pragma unroll
        for (int r = 0; r < 4; ++r) {
            int row = m0 + (r >> 1) * 16 + (r & 1) * 8 + qr;
            float4 p0 = *(float4*)&part[row * 4];
            float4 p1 = *(float4*)&part[row * 4 + 2];
            float S1 = p0.x + p0.z + p1.x + p1.z;
            float S2 = p0.y + p0.w + p1.y + p1.w;
            float m_ = S1 * (1.f / 256.f);
            mu[r] = m_;
            rs[r] = rsqrtf(fmaf(-m_, m_, S2 * (1.f / 256.f)) + 1e-5f);
        }
        __syncthreads();
#pragma unroll
        for (int nt = 0; nt < 8; ++nt) {
            int col = n0 + nt * 8 + qc * 2;
            float2 gg = *(const float2*)&gam[col];
            float2 ee = *(const float2*)&bet[col];
#pragma unroll
            for (int mt = 0; mt < 2; ++mt)
#pragma unroll
                for (int h = 0; h < 2; ++h) {
                    int r4 = mt * 2 + h;
                    int row = m0 + mt * 16 + h * 8 + qr;
                    float v0 = acc[mt][nt][2 * h], v1 = acc[mt][nt][2 * h + 1];
                    float y0 = fmaxf(fmaf((v0 - mu[r4]) * rs[r4], gg.x, ee.x), 0.f);
                    float y1 = fmaxf(fmaf((v1 - mu[r4]) * rs[r4], gg.y, ee.y), 0.f);
                    u32 off = (u32)row * XS_RS + (u32)col * 2;
                    if (res) {
                        u32 oh = *(u32*)(smc + XS_HI + off);
                        u32 ol = *(u32*)(smc + XS_LO + off);
                        y0 += bflo(oh) + bflo(ol);
                        y1 += bfhi(oh) + bfhi(ol);
                    }
                    u32 hh = packbf(y0, y1);
                    u32 ll = packbf(y0 - bflo(hh), y1 - bfhi(hh));
                    *(u32*)(smc + XS_HI + off) = hh;
                    *(u32*)(smc + XS_LO + off) = ll;
                }
        }
        __syncthreads();
    };

    // ---- pipeline: stem + 3 residual blocks ----
    gemm_run<256>(smb, smc, g_wimg + IMG_STEM, 2, acc, tid, m0, nq,
                  a_row, a_kh, b_n, b_kh);
    ep256(b_in, g_in, be_in, false);
    for (int b = 0; b < NBLK; ++b) {
        gemm_run<256>(smb, smc, g_wimg + IMG_BLK + (size_t)b * IMG_BLKSTR, 8,
                      acc, tid, m0, nq, a_row, a_kh, b_n, b_kh);
        ep256(bb + b * HID, gb + b * HID, betab + b * HID, true);
    }

    // ---- head GEMM + epilogue: z = LN(x@W_out+b_out) ----
    gemm_run<128>(smb, smc, g_wimg + IMG_HEAD, 8, acc, tid, m0, nq,
                  a_row, a_kh, b_n, b_kh);
    {
        const int n0 = nq * 32;
        float s1[4] = {0.f, 0.f, 0.f, 0.f}, s2[4] = {0.f, 0.f, 0.f, 0.f};
#pragma unroll
        for (int nt = 0; nt < 4; ++nt) {
            float2 bp = *(const float2*)&b_out[n0 + nt * 8 + qc * 2];
#pragma unroll
            for (int mt = 0; mt < 2; ++mt) {
                float* c = acc[mt][nt];
                c[0] += bp.x; c[1] += bp.y; c[2] += bp.x; c[3] += bp.y;
                s1[mt*2]   += c[0] + c[1];
                s2[mt*2]    = fmaf(c[0], c[0], fmaf(c[1], c[1], s2[mt*2]));
                s1[mt*2+1] += c[2] + c[3];
                s2[mt*2+1]  = fmaf(c[2], c[2], fmaf(c[3], c[3], s2[mt*2+1]));
            }
        }
#pragma unroll
        for (int r = 0; r < 4; ++r) {
            s1[r] += __shfl_xor_sync(0xffffffffu, s1[r], 1);
            s1[r] += __shfl_xor_sync(0xffffffffu, s1[r], 2);
            s2[r] += __shfl_xor_sync(0xffffffffu, s2[r], 1);
            s2[r] += __shfl_xor_sync(0xffffffffu, s2[r], 2);
        }
        if (qc == 0) {
#pragma unroll
            for (int r = 0; r < 4; ++r) {
                int row = m0 + (r >> 1) * 16 + (r & 1) * 8 + qr;
                part[row * 4 + nq] = make_float2(s1[r], s2[r]);
            }
        }
        __syncthreads();
        float mu[4], rs[4];
#pragma unroll
        for (int r = 0; r < 4; ++r) {
            int row = m0 + (r >> 1) * 16 + (r & 1) * 8 + qr;
            float4 p0 = *(float4*)&part[row * 4];
            float4 p1 = *(float4*)&part[row * 4 + 2];
            float S1 = p0.x + p0.z + p1.x + p1.z;
            float S2 = p0.y + p0.w + p1.y + p1.w;
            float m_ = S1 * (1.f / 128.f);
            mu[r] = m_;
            rs[r] = rsqrtf(fmaf(-m_, m_, S2 * (1.f / 128.f)) + 1e-5f);
        }
        __syncthreads();
        float* ztf = (float*)(smc + RING);     // zT[dim][132] fp32 (ring free)
        float sqp[4] = {0.f, 0.f, 0.f, 0.f};
#pragma unroll
        for (int nt = 0; nt < 4; ++nt) {
            int col = n0 + nt * 8 + qc * 2;
            float2 gg = *(const float2*)&g_out[col];
            float2 ee = *(const float2*)&be_out[col];
#pragma unroll
            for (int mt = 0; mt < 2; ++mt)
#pragma unroll
                for (int h = 0; h < 2; ++h) {
                    int r4 = mt * 2 + h;
                    int row = m0 + mt * 16 + h * 8 + qr;
                    float z0 = fmaf((acc[mt][nt][2*h]   - mu[r4]) * rs[r4], gg.x, ee.x);
                    float z1 = fmaf((acc[mt][nt][2*h+1] - mu[r4]) * rs[r4], gg.y, ee.y);
                    u32 off = (u32)row * XS_RS + (u32)col * 2;
                    u32 hh = packbf(z0, z1);
                    u32 ll = packbf(z0 - bflo(hh), z1 - bfhi(hh));
                    *(u32*)(smc + XS_HI + off) = hh;   // z planes overlay x
                    *(u32*)(smc + XS_LO + off) = ll;
                    ztf[col * 132 + row] = z0;
                    ztf[(col + 1) * 132 + row] = z1;
                    sqp[r4] = fmaf(z0, z0, fmaf(z1, z1, sqp[r4]));
                }
        }
#pragma unroll
        for (int r = 0; r < 4; ++r) {
            sqp[r] += __shfl_xor_sync(0xffffffffu, sqp[r], 1);
            sqp[r] += __shfl_xor_sync(0xffffffffu, sqp[r], 2);
        }
        if (qc == 0) {
#pragma unroll
            for (int r = 0; r < 4; ++r) {
                int row = m0 + (r >> 1) * 16 + (r & 1) * 8 + qr;
                part[row * 4 + nq].x = sqp[r];
            }
        }
        __syncthreads();
        if (nq == 0 && qc == 0) {
#pragma unroll
            for (int r = 0; r < 4; ++r) {
                int row = m0 + (r >> 1) * 16 + (r & 1) * 8 + qr;
                sqv[row] = part[row*4].x + part[row*4+1].x
                         + part[row*4+2].x + part[row*4+3].x;
            }
        }
        __syncthreads();
    }

    // ---- Gram: dot(i,j) = z_i . z_j via bf16x3 mma, term-major order ----
    {
#pragma unroll
        for (int mt = 0; mt < 2; ++mt)
#pragma unroll
            for (int nt = 0; nt < 4; ++nt)
#pragma unroll
                for (int e = 0; e < 4; ++e) acc[mt][nt][e] = 0.f;
        const int n0 = nq * 32;
        const u32 azh = smb + XS_HI + (u32)(m0 + a_row) * XS_RS + a_kh * 16;
        const u32 azl = azh + XS_PL;
        const u32 bzh = smb + XS_HI + (u32)(n0 + b_n) * XS_RS + b_kh * 16;
        const u32 bzl = bzh + XS_PL;
#pragma unroll
        for (int ks = 0; ks < 8; ++ks) {
            const u32 kb = (u32)ks * 32;
            u32 ah0[4], ah1[4], al0[4], al1[4];
            ldsm4(ah0, azh + kb);
            ldsm4(ah1, azh + 16 * XS_RS + kb);
            ldsm4(al0, azl + kb);
            ldsm4(al1, azl + 16 * XS_RS + kb);
            u32 bh[2][4], bl[2][4];
#pragma unroll
            for (int p = 0; p < 2; ++p) {
                ldsm4(bh[p], bzh + (u32)p * 16 * XS_RS + kb);
                ldsm4(bl[p], bzl + (u32)p * 16 * XS_RS + kb);
            }
            // term 1
#pragma unroll
            for (int p = 0; p < 2; ++p)
#pragma unroll
                for (int h = 0; h < 2; ++h) {
                    int nt = p * 2 + h;
                    mma16816(acc[0][nt], ah0, bh[p][2*h], bh[p][2*h+1]);
                    mma16816(acc[1][nt], ah1, bh[p][2*h], bh[p][2*h+1]);
                }
            // term 2
#pragma unroll
            for (int p = 0; p < 2; ++p)
#pragma unroll
                for (int h = 0; h < 2; ++h) {
                    int nt = p * 2 + h;
                    mma16816(acc[0][nt], al0, bh[p][2*h], bh[p][2*h+1]);
                    mma16816(acc[1][nt], al1, bh[p][2*h], bh[p][2*h+1]);
                }
            // term 3
#pragma unroll
            for (int p = 0; p < 2; ++p)
#pragma unroll
                for (int h = 0; h < 2; ++h) {
                    int nt = p * 2 + h;
                    mma16816(acc[0][nt], ah0, bl[p][2*h], bl[p][2*h+1]);
                    mma16816(acc[1][nt], ah1, bl[p][2*h], bl[p][2*h+1]);
                }
        }
        // distances -> per-row sums
        float sa[4] = {0.f, 0.f, 0.f, 0.f};
#pragma unroll
        for (int nt = 0; nt < 4; ++nt) {
            int col = n0 + nt * 8 + qc * 2;
            float sc0 = sqv[col], sc1 = sqv[col + 1];
#pragma unroll
            for (int mt = 0; mt < 2; ++mt)
#pragma unroll
                for (int h = 0; h < 2; ++h) {
                    int r4 = mt * 2 + h;
                    int row = m0 + mt * 16 + h * 8 + qr;
                    float sr = sqv[row];
                    float d0 = sr + sc0 - 2.f * acc[mt][nt][2 * h];
                    float d1 = sr + sc1 - 2.f * acc[mt][nt][2 * h + 1];
                    float t0 = (col == row) ? 1e-6f
                               : sqrtf(fmaxf(d0, 0.f) + 1e-12f);
                    float t1 = (col + 1 == row) ? 1e-6f
                               : sqrtf(fmaxf(d1, 0.f) + 1e-12f);
                    sa[r4] += t0 + t1;
                }
        }
#pragma unroll
        for (int r = 0; r < 4; ++r) {
            sa[r] += __shfl_xor_sync(0xffffffffu, sa[r], 1);
            sa[r] += __shfl_xor_sync(0xffffffffu, sa[r], 2);
        }
        if (qc == 0) {
#pragma unroll
            for (int r = 0; r < 4; ++r) {
                int row = m0 + (r >> 1) * 16 + (r & 1) * 8 + qr;
                part[row * 4 + nq].x = sa[r];
            }
        }
        __syncthreads();
        if (nq == 0 && qc == 0) {
#pragma unroll
            for (int r = 0; r < 4; ++r) {
                int row = m0 + (r >> 1) * 16 + (r & 1) * 8 + qr;
                ssm[row] = (part[row*4].x + part[row*4+1].x
                          + part[row*4+2].x + part[row*4+3].x) * (1.f / 128.f);
            }
        }
        __syncthreads();
    }

    // ---- softmax over 128 logits (warp 0) ----
    if (w == 0) {
        const float sc = 1.f / 0.25f;
        float sv[4], mx = -1e30f;
#pragma unroll
        for (int q = 0; q < 4; ++q) {
            sv[q] = ssm[lane + 32 * q] * sc;
            mx = fmaxf(mx, sv[q]);
        }
#pragma unroll
        for (int o = 16; o; o >>= 1)
            mx = fmaxf(mx, __shfl_xor_sync(0xffffffffu, mx, o));
        float e[4], se = 0.f;
#pragma unroll
        for (int q = 0; q < 4; ++q) { e[q] = expf(sv[q] - mx); se += e[q]; }
#pragma unroll
        for (int o = 16; o; o >>= 1) se += __shfl_xor_sync(0xffffffffu, se, o);
        float inv = 1.f / se;
#pragma unroll
        for (int q = 0; q < 4; ++q) {
            float ww = e[q] * inv;
            int i = lane + 32 * q;
            wsm[i] = ww;
            out[(size_t)NG * OUTD + (size_t)g * NODES + i] = ww;
        }
    }
    __syncthreads();

    // ---- v[d] = sum_i w_i * zT[d][i] ----
    if (tid < OUTD) {
        const float* ztf = (const float*)(smc + RING);
        float a = 0.f;
#pragma unroll 4
        for (int i = 0; i < NODES; ++i)
            a = fmaf(wsm[i], ztf[tid * 132 + i], a);
        out[(size_t)g * OUTD + tid] = a;
    }
}

}  // namespace lb

extern "C" void kernel_launch(void* const* d_in, const int* in_sizes, int n_in,
                              void* d_out, int out_size)
{
    (void)in_sizes; (void)n_in; (void)out_size;
    const float* H     = (const float*)d_in[0];
    const float* W_in  = (const float*)d_in[2];
    const float* b_in  = (const float*)d_in[3];
    const float* g_in  = (const float*)d_in[4];
    const float* be_in = (const float*)d_in[5];
    const float* Wb    = (const float*)d_in[6];
    const float* bb    = (const float*)d_in[7];
    const float* gb    = (const float*)d_in[8];
    const float* betab = (const float*)d_in[9];
    const float* W_out = (const float*)d_in[10];
    const float* b_out = (const float*)d_in[11];
    const float* g_out = (const float*)d_in[12];
    const float* be_out= (const float*)d_in[13];
    float* out = (float*)d_out;

    lb::prep<<<960, 256>>>(W_in, Wb, W_out);

    cudaFuncSetAttribute(lb::fused,
                         cudaFuncAttributeMaxDynamicSharedMemorySize,
                         lb::SMEM_BYTES);
    lb::fused<<<lb::NG, lb::TPB, lb::SMEM_BYTES>>>(
        H, b_in, g_in, be_in, bb, gb, betab, b_out, g_out, be_out, out);
}